// round 8
// baseline (speedup 1.0000x reference)
#include <cuda_runtime.h>
#include <cuda_fp16.h>
#include <cstdint>

#define BB 512
#define TT 256
#define CC 128
#define HH 128
#define BTH (BB * TT * HH)   // 16,777,216

// fp16 scratch (allocation-free rule: __device__ globals)
__device__ __half g_qh[(size_t)BTH];  // q * QS, [b][t][h]
__device__ __half g_kh[(size_t)BTH];  // k,      [b][t][h]
__device__ __half g_vt[(size_t)BTH];  // v,      [b][h][t]  (transposed)

__device__ __forceinline__ uint32_t h2bits(float a, float b) {
    __half2 h = __floats2half2_rn(a, b);
    return *(uint32_t*)&h;
}
__device__ __forceinline__ uint32_t smem_u32(const void* p) {
    uint32_t a;
    asm("{ .reg .u64 t; cvta.to.shared.u64 t, %1; cvt.u32.u64 %0, t; }" : "=r"(a) : "l"(p));
    return a;
}
__device__ __forceinline__ void cp_async16(uint32_t dst, const void* src) {
    asm volatile("cp.async.cg.shared.global [%0], [%1], 16;" :: "r"(dst), "l"(src));
}
#define CP_COMMIT() asm volatile("cp.async.commit_group;" ::: "memory")
#define CP_WAIT0()  asm volatile("cp.async.wait_group 0;" ::: "memory")

// m16n8k16 fp16 MMA, fp32 accumulate in place
__device__ __forceinline__ void mma_f16(float acc[4], const uint32_t a[4],
                                        uint32_t b0, uint32_t b1) {
    asm volatile(
        "mma.sync.aligned.m16n8k16.row.col.f32.f16.f16.f32 "
        "{%0,%1,%2,%3}, {%4,%5,%6,%7}, {%8,%9}, {%0,%1,%2,%3};"
        : "+f"(acc[0]), "+f"(acc[1]), "+f"(acc[2]), "+f"(acc[3])
        : "r"(a[0]), "r"(a[1]), "r"(a[2]), "r"(a[3]), "r"(b0), "r"(b1));
}

// scale * log2(e): softmax computed base-2; folded into q at projection time
#define QSCALE (0.08838834764831845f * 1.4426950408889634f)

// ===========================================================================
// Kernel 1: projection (fp16 mma), 2 row-tiles per CTA, cp.async-pipelined.
// Grid 512, 256 threads, 8 warps = 4 m-groups x 2 n-groups.
// smem: stage fp32 [128][132] (66KB) + xs/ws0/ws1/ws2 fp16 [128][136] (136KB)
//       = 202KB.  W loaded+converted once per CTA; x tile1 prefetched via
//       cp.async during tile0's mma phase.
// ===========================================================================
#define LDA32 132
#define LDH   136
#define STAGE_FLOATS (128 * LDA32)
#define PROJ_SMEM (STAGE_FLOATS * 4 + 4 * 128 * LDH * 2)

__device__ __forceinline__ void load_w_t(const float* __restrict__ W,
                                         __half* __restrict__ ws, int tid) {
#pragma unroll
    for (int j = 0; j < 16; j++) {
        int i  = tid + j * 256;        // 0..4095
        int n  = i & 127;
        int kq = i >> 7;               // 0..31
        float w0 = W[(kq * 4 + 0) * HH + n];
        float w1 = W[(kq * 4 + 1) * HH + n];
        float w2 = W[(kq * 4 + 2) * HH + n];
        float w3 = W[(kq * 4 + 3) * HH + n];
        uint2 p = {h2bits(w0, w1), h2bits(w2, w3)};
        *(uint2*)&ws[n * LDH + kq * 4] = p;
    }
}

__device__ __forceinline__ void cp_x_tile(uint32_t stage_addr,
                                          const float* __restrict__ xsrc, int tid) {
#pragma unroll
    for (int j = 0; j < 16; j++) {
        int i4  = tid + j * 256;
        int row = i4 >> 5;
        int c4  = (i4 & 31) * 4;
        cp_async16(stage_addr + (uint32_t)(row * LDA32 + c4) * 4u,
                   (const char*)xsrc + (size_t)i4 * 16);
    }
    CP_COMMIT();
}

__device__ __forceinline__ void cvt_stage_to_xs(const float* __restrict__ stage,
                                                __half* __restrict__ xs, int tid) {
#pragma unroll
    for (int j = 0; j < 16; j++) {
        int i4  = tid + j * 256;
        int row = i4 >> 5;
        int c4  = (i4 & 31) * 4;
        float4 v = *(const float4*)&stage[row * LDA32 + c4];
        uint2 p = {h2bits(v.x, v.y), h2bits(v.z, v.w)};
        *(uint2*)&xs[row * LDH + c4] = p;
    }
}

// Full K/Q/V compute + all epilogues for one 128-row tile resident in xs.
__device__ __forceinline__ void proj_tile(const __half* __restrict__ xs,
                                          const __half* __restrict__ ws0,
                                          const __half* __restrict__ ws1,
                                          const __half* __restrict__ ws2,
                                          float* __restrict__ kout,
                                          float* __restrict__ vout,
                                          int tile, int mbase, int nbase,
                                          int g, int c) {
    // ---- fused K+Q mma (8 k-steps of k16) ----
    float ak[2][8][4], aq[2][8][4];
#pragma unroll
    for (int mt = 0; mt < 2; mt++)
#pragma unroll
        for (int nt = 0; nt < 8; nt++)
#pragma unroll
            for (int e = 0; e < 4; e++) { ak[mt][nt][e] = 0.0f; aq[mt][nt][e] = 0.0f; }

#pragma unroll
    for (int kk = 0; kk < 8; kk++) {
        uint32_t a[2][4];
#pragma unroll
        for (int mt = 0; mt < 2; mt++) {
            const __half* xr = xs + (mbase + mt * 16 + g) * LDH + kk * 16 + 2 * c;
            a[mt][0] = *(const uint32_t*)(xr);
            a[mt][1] = *(const uint32_t*)(xr + 8 * LDH);
            a[mt][2] = *(const uint32_t*)(xr + 8);
            a[mt][3] = *(const uint32_t*)(xr + 8 * LDH + 8);
        }
#pragma unroll
        for (int nt = 0; nt < 8; nt++) {
            const __half* w0p = ws0 + (nbase + nt * 8 + g) * LDH + kk * 16 + 2 * c;
            const __half* w1p = ws1 + (nbase + nt * 8 + g) * LDH + kk * 16 + 2 * c;
            uint32_t bk0 = *(const uint32_t*)(w0p), bk1 = *(const uint32_t*)(w0p + 8);
            uint32_t bq0 = *(const uint32_t*)(w1p), bq1 = *(const uint32_t*)(w1p + 8);
            mma_f16(ak[0][nt], a[0], bk0, bk1);
            mma_f16(ak[1][nt], a[1], bk0, bk1);
            mma_f16(aq[0][nt], a[0], bq0, bq1);
            mma_f16(aq[1][nt], a[1], bq0, bq1);
        }
    }

    // K epilogue (fp32 + fp16) and Q epilogue (fp16 scaled)
#pragma unroll
    for (int mt = 0; mt < 2; mt++) {
#pragma unroll
        for (int nt = 0; nt < 8; nt++) {
            int row = tile * 128 + mbase + mt * 16 + g;
            int col = nbase + nt * 8 + 2 * c;
            const float* kk4 = ak[mt][nt];
            *(float2*)(kout + (size_t)row * HH + col)       = make_float2(kk4[0], kk4[1]);
            *(float2*)(kout + (size_t)(row + 8) * HH + col) = make_float2(kk4[2], kk4[3]);
            *(uint32_t*)&g_kh[(size_t)row * HH + col]       = h2bits(kk4[0], kk4[1]);
            *(uint32_t*)&g_kh[(size_t)(row + 8) * HH + col] = h2bits(kk4[2], kk4[3]);
            const float* q4 = aq[mt][nt];
            *(uint32_t*)&g_qh[(size_t)row * HH + col]       = h2bits(q4[0] * QSCALE, q4[1] * QSCALE);
            *(uint32_t*)&g_qh[(size_t)(row + 8) * HH + col] = h2bits(q4[2] * QSCALE, q4[3] * QSCALE);
        }
    }

    // ---- V phase ----
    float av[2][8][4];
#pragma unroll
    for (int mt = 0; mt < 2; mt++)
#pragma unroll
        for (int nt = 0; nt < 8; nt++)
#pragma unroll
            for (int e = 0; e < 4; e++) av[mt][nt][e] = 0.0f;

#pragma unroll
    for (int kk = 0; kk < 8; kk++) {
        uint32_t a[2][4];
#pragma unroll
        for (int mt = 0; mt < 2; mt++) {
            const __half* xr = xs + (mbase + mt * 16 + g) * LDH + kk * 16 + 2 * c;
            a[mt][0] = *(const uint32_t*)(xr);
            a[mt][1] = *(const uint32_t*)(xr + 8 * LDH);
            a[mt][2] = *(const uint32_t*)(xr + 8);
            a[mt][3] = *(const uint32_t*)(xr + 8 * LDH + 8);
        }
#pragma unroll
        for (int nt = 0; nt < 8; nt++) {
            const __half* wp = ws2 + (nbase + nt * 8 + g) * LDH + kk * 16 + 2 * c;
            uint32_t b0 = *(const uint32_t*)(wp), b1 = *(const uint32_t*)(wp + 8);
            mma_f16(av[0][nt], a[0], b0, b1);
            mma_f16(av[1][nt], a[1], b0, b1);
        }
    }

    // V epilogue: fp32 coalesced + fp16 transposed direct (sector-granular)
    {
        const size_t vb  = (size_t)(tile >> 1) * 128 * 256;
        const int    ltb = (tile & 1) * 128;
#pragma unroll
        for (int mt = 0; mt < 2; mt++) {
#pragma unroll
            for (int nt = 0; nt < 8; nt++) {
                int rloc = mbase + mt * 16 + g;
                int row  = tile * 128 + rloc;
                int lt   = ltb + rloc;
                int col  = nbase + nt * 8 + 2 * c;
                const float* v4 = av[mt][nt];
                *(float2*)(vout + (size_t)row * HH + col)       = make_float2(v4[0], v4[1]);
                *(float2*)(vout + (size_t)(row + 8) * HH + col) = make_float2(v4[2], v4[3]);
                g_vt[vb + (size_t)col * 256 + lt]           = __float2half_rn(v4[0]);
                g_vt[vb + (size_t)(col + 1) * 256 + lt]     = __float2half_rn(v4[1]);
                g_vt[vb + (size_t)col * 256 + lt + 8]       = __float2half_rn(v4[2]);
                g_vt[vb + (size_t)(col + 1) * 256 + lt + 8] = __float2half_rn(v4[3]);
            }
        }
    }
}

__global__ void __launch_bounds__(256, 1)
proj_mma(const float* __restrict__ x,
         const float* __restrict__ Wk,
         const float* __restrict__ Wq,
         const float* __restrict__ Wv,
         float* __restrict__ kout,
         float* __restrict__ vout)
{
    extern __shared__ char smraw[];
    float*  stage = (float*)smraw;                         // [128][132] fp32
    __half* xs  = (__half*)(smraw + STAGE_FLOATS * 4);     // [128][136]
    __half* ws0 = xs  + 128 * LDH;
    __half* ws1 = ws0 + 128 * LDH;
    __half* ws2 = ws1 + 128 * LDH;

    const int tid   = threadIdx.x;
    const int tile0 = blockIdx.x * 2;
    const int w     = tid >> 5;
    const int lane  = tid & 31;
    const int g     = lane >> 2;
    const int c     = lane & 3;
    const int mbase = (w >> 1) * 32;
    const int nbase = (w & 1) * 64;

    const uint32_t stage_a = smem_u32(stage);

    // x tile0 in flight while W is loaded+converted
    cp_x_tile(stage_a, x + (size_t)tile0 * 128 * CC, tid);
    load_w_t(Wk, ws0, tid);
    load_w_t(Wq, ws1, tid);
    load_w_t(Wv, ws2, tid);
    CP_WAIT0();
    __syncthreads();

    cvt_stage_to_xs(stage, xs, tid);
    __syncthreads();

    // prefetch x tile1 into stage; overlaps tile0 compute
    cp_x_tile(stage_a, x + (size_t)(tile0 + 1) * 128 * CC, tid);

    proj_tile(xs, ws0, ws1, ws2, kout, vout, tile0, mbase, nbase, g, c);

    CP_WAIT0();
    __syncthreads();       // all tile0 xs reads done; x1 landed
    cvt_stage_to_xs(stage, xs, tid);
    __syncthreads();

    proj_tile(xs, ws0, ws1, ws2, kout, vout, tile0 + 1, mbase, nbase, g, c);
}

// ===========================================================================
// Kernel 2: causal flash attention (unchanged from R7/R5).
// ===========================================================================
#define LKH 136
#define LVH 72
#define LPH 72
#define KBUF (64 * LKH)
#define VBUF (128 * LVH)
#define ATTN_SMEM ((2 * KBUF + 2 * VBUF + 128 * LPH) * 2)
#define NEG_BIG (-1.0e30f)

__global__ void __launch_bounds__(256, 1)
attn_mma(float* __restrict__ outg)
{
    extern __shared__ __half smh[];
    __half* Ks = smh;                 // [2][64][136]
    __half* Vt = Ks + 2 * KBUF;       // [2][128][72]
    __half* Ps = Vt + 2 * VBUF;       // [128][72]

    const int tid  = threadIdx.x;
    const int qt   = blockIdx.x;      // 0..1
    const int b    = blockIdx.y;      // 0..511
    const int w    = tid >> 5;
    const int lane = tid & 31;
    const int g    = lane >> 2;
    const int c    = lane & 3;
    const int rb   = w * 16;

    const uint32_t ks_a = smem_u32(Ks);
    const uint32_t vt_a = smem_u32(Vt);

    const __half* kh = g_kh + (size_t)b * TT * HH;      // [t][h]
    const __half* vt = g_vt + (size_t)b * 128 * 256;    // [h][t]
    const int nkt = qt ? 4 : 2;

    auto cp_stage = [&](int st) {
        uint32_t kd = ks_a + (uint32_t)((st & 1) * KBUF) * 2u;
        uint32_t vd = vt_a + (uint32_t)((st & 1) * VBUF) * 2u;
#pragma unroll
        for (int j = 0; j < 4; j++) {
            int i4 = tid + j * 256;
            int kr = i4 >> 4, kc = i4 & 15;
            cp_async16(kd + (uint32_t)(kr * LKH + kc * 8) * 2u,
                       kh + (size_t)(st * 64 + kr) * HH + kc * 8);
            int vr = i4 >> 3, vc = i4 & 7;
            cp_async16(vd + (uint32_t)(vr * LVH + vc * 8) * 2u,
                       vt + (size_t)vr * 256 + st * 64 + vc * 8);
        }
        CP_COMMIT();
    };

    cp_stage(0);

    // Q fragments -> registers
    uint32_t aq[8][4];
    {
        const __half* q0 = g_qh + ((size_t)b * TT + qt * 128 + rb + g) * HH + 2 * c;
        const __half* q1 = q0 + 8 * HH;
#pragma unroll
        for (int kk = 0; kk < 8; kk++) {
            aq[kk][0] = *(const uint32_t*)(q0 + kk * 16);
            aq[kk][1] = *(const uint32_t*)(q1 + kk * 16);
            aq[kk][2] = *(const uint32_t*)(q0 + kk * 16 + 8);
            aq[kk][3] = *(const uint32_t*)(q1 + kk * 16 + 8);
        }
    }

    float m0 = NEG_BIG, m1 = NEG_BIG, l0 = 0.0f, l1 = 0.0f;
    float o[16][4];
#pragma unroll
    for (int nt = 0; nt < 16; nt++)
#pragma unroll
        for (int e = 0; e < 4; e++) o[nt][e] = 0.0f;

    const int row0 = qt * 128 + rb + g;
    const int row1 = row0 + 8;

    for (int st = 0; st < nkt; st++) {
        CP_WAIT0();
        __syncthreads();
        if (st + 1 < nkt) cp_stage(st + 1);

        const __half* Kb = Ks + (st & 1) * KBUF;
        const __half* Vb = Vt + (st & 1) * VBUF;

        // S = Q K^T
        float s[8][4];
#pragma unroll
        for (int nt = 0; nt < 8; nt++)
#pragma unroll
            for (int e = 0; e < 4; e++) s[nt][e] = 0.0f;

#pragma unroll
        for (int kk = 0; kk < 8; kk++) {
#pragma unroll
            for (int nt = 0; nt < 8; nt++) {
                const __half* kr = Kb + (nt * 8 + g) * LKH + kk * 16 + 2 * c;
                uint32_t b0 = *(const uint32_t*)(kr);
                uint32_t b1 = *(const uint32_t*)(kr + 8);
                mma_f16(s[nt], aq[kk], b0, b1);
            }
        }

        // causal mask + online softmax (base 2, Q pre-scaled)
        float mx0 = NEG_BIG, mx1 = NEG_BIG;
#pragma unroll
        for (int nt = 0; nt < 8; nt++) {
            int k0 = st * 64 + nt * 8 + 2 * c;
            s[nt][0] = (k0     <= row0) ? s[nt][0] : NEG_BIG;
            s[nt][1] = (k0 + 1 <= row0) ? s[nt][1] : NEG_BIG;
            s[nt][2] = (k0     <= row1) ? s[nt][2] : NEG_BIG;
            s[nt][3] = (k0 + 1 <= row1) ? s[nt][3] : NEG_BIG;
            mx0 = fmaxf(mx0, fmaxf(s[nt][0], s[nt][1]));
            mx1 = fmaxf(mx1, fmaxf(s[nt][2], s[nt][3]));
        }
#pragma unroll
        for (int off = 1; off < 4; off <<= 1) {
            mx0 = fmaxf(mx0, __shfl_xor_sync(0xffffffffu, mx0, off));
            mx1 = fmaxf(mx1, __shfl_xor_sync(0xffffffffu, mx1, off));
        }
        float mn0 = fmaxf(m0, mx0);
        float mn1 = fmaxf(m1, mx1);
        float al0 = exp2f(m0 - mn0);
        float al1 = exp2f(m1 - mn1);
        float ps0 = 0.0f, ps1 = 0.0f;
#pragma unroll
        for (int nt = 0; nt < 8; nt++) {
            s[nt][0] = exp2f(s[nt][0] - mn0);
            s[nt][1] = exp2f(s[nt][1] - mn0);
            s[nt][2] = exp2f(s[nt][2] - mn1);
            s[nt][3] = exp2f(s[nt][3] - mn1);
            ps0 += s[nt][0] + s[nt][1];
            ps1 += s[nt][2] + s[nt][3];
        }
#pragma unroll
        for (int off = 1; off < 4; off <<= 1) {
            ps0 += __shfl_xor_sync(0xffffffffu, ps0, off);
            ps1 += __shfl_xor_sync(0xffffffffu, ps1, off);
        }
        l0 = l0 * al0 + ps0;
        l1 = l1 * al1 + ps1;
        m0 = mn0;
        m1 = mn1;
#pragma unroll
        for (int nt = 0; nt < 16; nt++) {
            o[nt][0] *= al0;
            o[nt][1] *= al0;
            o[nt][2] *= al1;
            o[nt][3] *= al1;
        }

        // stage P (fp16)
#pragma unroll
        for (int nt = 0; nt < 8; nt++) {
            *(uint32_t*)&Ps[(rb + g) * LPH + nt * 8 + 2 * c]     = h2bits(s[nt][0], s[nt][1]);
            *(uint32_t*)&Ps[(rb + g + 8) * LPH + nt * 8 + 2 * c] = h2bits(s[nt][2], s[nt][3]);
        }
        __syncwarp();

        // O += P @ V
#pragma unroll
        for (int kk = 0; kk < 4; kk++) {
            uint32_t a[4];
            const __half* pr = Ps + (rb + g) * LPH + kk * 16 + 2 * c;
            a[0] = *(const uint32_t*)(pr);
            a[1] = *(const uint32_t*)(pr + 8 * LPH);
            a[2] = *(const uint32_t*)(pr + 8);
            a[3] = *(const uint32_t*)(pr + 8 * LPH + 8);
#pragma unroll
            for (int nt = 0; nt < 16; nt++) {
                const __half* vr = Vb + (nt * 8 + g) * LVH + kk * 16 + 2 * c;
                uint32_t b0 = *(const uint32_t*)(vr);
                uint32_t b1 = *(const uint32_t*)(vr + 8);
                mma_f16(o[nt], a, b0, b1);
            }
        }
    }

    // normalize + write
    float inv0 = 1.0f / l0;
    float inv1 = 1.0f / l1;
    float* orow0 = outg + ((size_t)b * TT + qt * 128 + rb + g) * HH;
    float* orow1 = orow0 + 8 * HH;
#pragma unroll
    for (int nt = 0; nt < 16; nt++) {
        int col = nt * 8 + 2 * c;
        *(float2*)(orow0 + col) = make_float2(o[nt][0] * inv0, o[nt][1] * inv0);
        *(float2*)(orow1 + col) = make_float2(o[nt][2] * inv1, o[nt][3] * inv1);
    }
}

// ===========================================================================
extern "C" void kernel_launch(void* const* d_in, const int* in_sizes, int n_in,
                              void* d_out, int out_size)
{
    const float* x  = (const float*)d_in[0];
    const float* Wk = (const float*)d_in[1];
    const float* Wq = (const float*)d_in[2];
    const float* Wv = (const float*)d_in[3];

    float* out  = (float*)d_out;
    float* kout = out + (size_t)BTH;
    float* vout = out + 2 * (size_t)BTH;

    cudaFuncSetAttribute(proj_mma, cudaFuncAttributeMaxDynamicSharedMemorySize, PROJ_SMEM);
    cudaFuncSetAttribute(attn_mma, cudaFuncAttributeMaxDynamicSharedMemorySize, ATTN_SMEM);

    proj_mma<<<512, 256, PROJ_SMEM>>>(x, Wk, Wq, Wv, kout, vout);
    attn_mma<<<dim3(2, 512), 256, ATTN_SMEM>>>(out);
}

// round 9
// speedup vs baseline: 1.1445x; 1.1445x over previous
#include <cuda_runtime.h>
#include <cuda_fp16.h>
#include <cstdint>

#define BB 512
#define TT 256
#define CC 128
#define HH 128
#define BTH (BB * TT * HH)   // 16,777,216

// q fp16 scratch (cross-warp layout exchange; L2-hot)
__device__ __half g_qh[(size_t)BTH];  // q * QSCALE, [b][t][h]

__device__ __forceinline__ uint32_t h2bits(float a, float b) {
    __half2 h = __floats2half2_rn(a, b);
    return *(uint32_t*)&h;
}

// m16n8k16 fp16 MMA, fp32 accumulate in place
__device__ __forceinline__ void mma_f16(float acc[4], const uint32_t a[4],
                                        uint32_t b0, uint32_t b1) {
    asm volatile(
        "mma.sync.aligned.m16n8k16.row.col.f32.f16.f16.f32 "
        "{%0,%1,%2,%3}, {%4,%5,%6,%7}, {%8,%9}, {%0,%1,%2,%3};"
        : "+f"(acc[0]), "+f"(acc[1]), "+f"(acc[2]), "+f"(acc[3])
        : "r"(a[0]), "r"(a[1]), "r"(a[2]), "r"(a[3]), "r"(b0), "r"(b1));
}

// scale * log2(e): softmax computed base-2; folded into q at projection time
#define QSCALE (0.08838834764831845f * 1.4426950408889634f)

// ===========================================================================
// Fused kernel: one CTA per batch (512 CTAs, 256 threads).
//   Phase P: project k/q/v for all 256 tokens (2 half-tiles x 3 W phases).
//            k -> kout(fp32 global) + ksm(fp16 smem [256][136])
//            q -> g_qh (fp16 global, pre-scaled)
//            v -> vout(fp32 global) + vtsm(fp16 smem transposed [128][264])
//   Phase A: causal flash attention entirely out of smem (2 q-tile passes,
//            P warp-private in Pbuf overlaying Wbuf).
// smem halves: xbuf[128][136] + Wbuf[128][136] + ksm[256][136] + vtsm[128][264]
//            = 103,424 halves = 206,848 B
// ===========================================================================
#define LWB 136
#define LVT 264
#define LPH 72
#define XBUF_OFF 0
#define WBUF_OFF (128 * LWB)
#define KSM_OFF  (WBUF_OFF + 128 * LWB)
#define VT_OFF   (KSM_OFF + 256 * LWB)
#define FUSED_SMEM ((VT_OFF + 128 * LVT) * 2)
#define NEG_BIG (-1.0e30f)

__device__ __forceinline__ void load_w_t(const float* __restrict__ W,
                                         __half* __restrict__ ws, int tid) {
#pragma unroll
    for (int j = 0; j < 16; j++) {
        int i  = tid + j * 256;        // 0..4095
        int n  = i & 127;
        int kq = i >> 7;               // 0..31
        float w0 = W[(kq * 4 + 0) * HH + n];
        float w1 = W[(kq * 4 + 1) * HH + n];
        float w2 = W[(kq * 4 + 2) * HH + n];
        float w3 = W[(kq * 4 + 3) * HH + n];
        uint2 p = {h2bits(w0, w1), h2bits(w2, w3)};
        *(uint2*)&ws[n * LWB + kq * 4] = p;
    }
}

__global__ void __launch_bounds__(256, 1)
fused_head(const float* __restrict__ x,
           const float* __restrict__ Wk,
           const float* __restrict__ Wq,
           const float* __restrict__ Wv,
           float* __restrict__ outg,
           float* __restrict__ kout,
           float* __restrict__ vout)
{
    extern __shared__ __half smh[];
    __half* xbuf = smh + XBUF_OFF;    // [128][136]
    __half* Wbuf = smh + WBUF_OFF;    // [128][136]; Pbuf overlay during attn
    __half* ksm  = smh + KSM_OFF;     // [256][136]
    __half* vtsm = smh + VT_OFF;      // [128][264]  (head dim major, token minor)
    __half* Pbuf = Wbuf;              // [128][72]

    const int tid  = threadIdx.x;
    const int b    = blockIdx.x;      // batch
    const int w    = tid >> 5;
    const int lane = tid & 31;
    const int g    = lane >> 2;
    const int c    = lane & 3;
    const int mbase = (w >> 1) * 32;  // proj: warp's row group within half-tile
    const int nbase = (w & 1) * 64;   // proj: warp's col group
    const int rb   = w * 16;          // attn: warp's q-row base within q-tile

    // =======================================================================
    // Phase P: projection
    // =======================================================================
#pragma unroll 1
    for (int half = 0; half < 2; half++) {
        __syncthreads();   // xbuf/Wbuf reuse across halves

        // x half-tile -> xbuf (fp16)
        {
            const float4* xg = (const float4*)(x + ((size_t)b * TT + half * 128) * CC);
#pragma unroll
            for (int j = 0; j < 16; j++) {
                int i4 = tid + j * 256;
                float4 v = xg[i4];
                int row = i4 >> 5;
                int c4  = (i4 & 31) * 4;
                uint2 p = {h2bits(v.x, v.y), h2bits(v.z, v.w)};
                *(uint2*)&xbuf[row * LWB + c4] = p;
            }
        }

#pragma unroll 1
        for (int ph = 0; ph < 3; ph++) {
            __syncthreads();   // previous Wbuf readers done; xbuf visible (ph=0)
            load_w_t(ph == 0 ? Wk : (ph == 1 ? Wq : Wv), Wbuf, tid);
            __syncthreads();

            float acc[2][8][4];
#pragma unroll
            for (int mt = 0; mt < 2; mt++)
#pragma unroll
                for (int nt = 0; nt < 8; nt++)
#pragma unroll
                    for (int e = 0; e < 4; e++) acc[mt][nt][e] = 0.0f;

#pragma unroll
            for (int kk = 0; kk < 8; kk++) {
                uint32_t a[2][4];
#pragma unroll
                for (int mt = 0; mt < 2; mt++) {
                    const __half* xr = xbuf + (mbase + mt * 16 + g) * LWB + kk * 16 + 2 * c;
                    a[mt][0] = *(const uint32_t*)(xr);
                    a[mt][1] = *(const uint32_t*)(xr + 8 * LWB);
                    a[mt][2] = *(const uint32_t*)(xr + 8);
                    a[mt][3] = *(const uint32_t*)(xr + 8 * LWB + 8);
                }
#pragma unroll
                for (int nt = 0; nt < 8; nt++) {
                    const __half* wp = Wbuf + (nbase + nt * 8 + g) * LWB + kk * 16 + 2 * c;
                    uint32_t b0 = *(const uint32_t*)(wp), b1 = *(const uint32_t*)(wp + 8);
                    mma_f16(acc[0][nt], a[0], b0, b1);
                    mma_f16(acc[1][nt], a[1], b0, b1);
                }
            }

            // epilogue
#pragma unroll
            for (int mt = 0; mt < 2; mt++) {
#pragma unroll
                for (int nt = 0; nt < 8; nt++) {
                    int rloc = mbase + mt * 16 + g;           // 0..127 within half
                    int t    = half * 128 + rloc;             // token within batch
                    int grow = b * TT + t;                    // global row
                    int col  = nbase + nt * 8 + 2 * c;
                    const float* v4 = acc[mt][nt];
                    if (ph == 0) {          // k
                        *(float2*)(kout + (size_t)grow * HH + col)       = make_float2(v4[0], v4[1]);
                        *(float2*)(kout + (size_t)(grow + 8) * HH + col) = make_float2(v4[2], v4[3]);
                        *(uint32_t*)&ksm[t * LWB + col]       = h2bits(v4[0], v4[1]);
                        *(uint32_t*)&ksm[(t + 8) * LWB + col] = h2bits(v4[2], v4[3]);
                    } else if (ph == 1) {   // q (pre-scaled)
                        *(uint32_t*)&g_qh[(size_t)grow * HH + col]       = h2bits(v4[0] * QSCALE, v4[1] * QSCALE);
                        *(uint32_t*)&g_qh[(size_t)(grow + 8) * HH + col] = h2bits(v4[2] * QSCALE, v4[3] * QSCALE);
                    } else {                // v
                        *(float2*)(vout + (size_t)grow * HH + col)       = make_float2(v4[0], v4[1]);
                        *(float2*)(vout + (size_t)(grow + 8) * HH + col) = make_float2(v4[2], v4[3]);
                        vtsm[(col    ) * LVT + t]     = __float2half_rn(v4[0]);
                        vtsm[(col + 1) * LVT + t]     = __float2half_rn(v4[1]);
                        vtsm[(col    ) * LVT + t + 8] = __float2half_rn(v4[2]);
                        vtsm[(col + 1) * LVT + t + 8] = __float2half_rn(v4[3]);
                    }
                }
            }
        }
    }
    __syncthreads();   // ksm/vtsm complete + g_qh globally visible within CTA

    // =======================================================================
    // Phase A: causal flash attention (all K/V resident in smem)
    // =======================================================================
#pragma unroll 1
    for (int qt = 0; qt < 2; qt++) {
        // Q fragments -> registers
        uint32_t aq[8][4];
        {
            const __half* q0 = g_qh + ((size_t)b * TT + qt * 128 + rb + g) * HH + 2 * c;
            const __half* q1 = q0 + 8 * HH;
#pragma unroll
            for (int kk = 0; kk < 8; kk++) {
                aq[kk][0] = *(const uint32_t*)(q0 + kk * 16);
                aq[kk][1] = *(const uint32_t*)(q1 + kk * 16);
                aq[kk][2] = *(const uint32_t*)(q0 + kk * 16 + 8);
                aq[kk][3] = *(const uint32_t*)(q1 + kk * 16 + 8);
            }
        }

        float m0 = NEG_BIG, m1 = NEG_BIG, l0 = 0.0f, l1 = 0.0f;
        float o[16][4];
#pragma unroll
        for (int nt = 0; nt < 16; nt++)
#pragma unroll
            for (int e = 0; e < 4; e++) o[nt][e] = 0.0f;

        const int row0 = qt * 128 + rb + g;
        const int row1 = row0 + 8;
        const int nkt  = 2 * (qt + 1);

#pragma unroll 1
        for (int kt = 0; kt < nkt; kt++) {
            // ---- S = Q K^T (B from resident ksm) ----
            float s[8][4];
#pragma unroll
            for (int nt = 0; nt < 8; nt++)
#pragma unroll
                for (int e = 0; e < 4; e++) s[nt][e] = 0.0f;

#pragma unroll
            for (int kk = 0; kk < 8; kk++) {
#pragma unroll
                for (int nt = 0; nt < 8; nt++) {
                    const __half* kr = ksm + (kt * 64 + nt * 8 + g) * LWB + kk * 16 + 2 * c;
                    uint32_t b0 = *(const uint32_t*)(kr);
                    uint32_t b1 = *(const uint32_t*)(kr + 8);
                    mma_f16(s[nt], aq[kk], b0, b1);
                }
            }

            // ---- causal mask + online softmax (base 2, Q pre-scaled) ----
            float mx0 = NEG_BIG, mx1 = NEG_BIG;
#pragma unroll
            for (int nt = 0; nt < 8; nt++) {
                int k0 = kt * 64 + nt * 8 + 2 * c;
                s[nt][0] = (k0     <= row0) ? s[nt][0] : NEG_BIG;
                s[nt][1] = (k0 + 1 <= row0) ? s[nt][1] : NEG_BIG;
                s[nt][2] = (k0     <= row1) ? s[nt][2] : NEG_BIG;
                s[nt][3] = (k0 + 1 <= row1) ? s[nt][3] : NEG_BIG;
                mx0 = fmaxf(mx0, fmaxf(s[nt][0], s[nt][1]));
                mx1 = fmaxf(mx1, fmaxf(s[nt][2], s[nt][3]));
            }
#pragma unroll
            for (int off = 1; off < 4; off <<= 1) {
                mx0 = fmaxf(mx0, __shfl_xor_sync(0xffffffffu, mx0, off));
                mx1 = fmaxf(mx1, __shfl_xor_sync(0xffffffffu, mx1, off));
            }
            float mn0 = fmaxf(m0, mx0);
            float mn1 = fmaxf(m1, mx1);
            float al0 = exp2f(m0 - mn0);
            float al1 = exp2f(m1 - mn1);
            float ps0 = 0.0f, ps1 = 0.0f;
#pragma unroll
            for (int nt = 0; nt < 8; nt++) {
                s[nt][0] = exp2f(s[nt][0] - mn0);
                s[nt][1] = exp2f(s[nt][1] - mn0);
                s[nt][2] = exp2f(s[nt][2] - mn1);
                s[nt][3] = exp2f(s[nt][3] - mn1);
                ps0 += s[nt][0] + s[nt][1];
                ps1 += s[nt][2] + s[nt][3];
            }
#pragma unroll
            for (int off = 1; off < 4; off <<= 1) {
                ps0 += __shfl_xor_sync(0xffffffffu, ps0, off);
                ps1 += __shfl_xor_sync(0xffffffffu, ps1, off);
            }
            l0 = l0 * al0 + ps0;
            l1 = l1 * al1 + ps1;
            m0 = mn0;
            m1 = mn1;
#pragma unroll
            for (int nt = 0; nt < 16; nt++) {
                o[nt][0] *= al0;
                o[nt][1] *= al0;
                o[nt][2] *= al1;
                o[nt][3] *= al1;
            }

            // ---- stage P (warp-private rows of Pbuf) ----
#pragma unroll
            for (int nt = 0; nt < 8; nt++) {
                *(uint32_t*)&Pbuf[(rb + g) * LPH + nt * 8 + 2 * c]     = h2bits(s[nt][0], s[nt][1]);
                *(uint32_t*)&Pbuf[(rb + g + 8) * LPH + nt * 8 + 2 * c] = h2bits(s[nt][2], s[nt][3]);
            }
            __syncwarp();

            // ---- O += P @ V (B from resident vtsm) ----
#pragma unroll
            for (int kk = 0; kk < 4; kk++) {
                uint32_t a[4];
                const __half* pr = Pbuf + (rb + g) * LPH + kk * 16 + 2 * c;
                a[0] = *(const uint32_t*)(pr);
                a[1] = *(const uint32_t*)(pr + 8 * LPH);
                a[2] = *(const uint32_t*)(pr + 8);
                a[3] = *(const uint32_t*)(pr + 8 * LPH + 8);
#pragma unroll
                for (int nt = 0; nt < 16; nt++) {
                    const __half* vr = vtsm + (nt * 8 + g) * LVT + kt * 64 + kk * 16 + 2 * c;
                    uint32_t b0 = *(const uint32_t*)(vr);
                    uint32_t b1 = *(const uint32_t*)(vr + 8);
                    mma_f16(o[nt], a, b0, b1);
                }
            }
            __syncwarp();   // Pbuf rows reused next kt by this warp only
        }

        // ---- normalize + write ----
        float inv0 = 1.0f / l0;
        float inv1 = 1.0f / l1;
        float* orow0 = outg + ((size_t)b * TT + qt * 128 + rb + g) * HH;
        float* orow1 = orow0 + 8 * HH;
#pragma unroll
        for (int nt = 0; nt < 16; nt++) {
            int col = nt * 8 + 2 * c;
            *(float2*)(orow0 + col) = make_float2(o[nt][0] * inv0, o[nt][1] * inv0);
            *(float2*)(orow1 + col) = make_float2(o[nt][2] * inv1, o[nt][3] * inv1);
        }
    }
}

// ===========================================================================
extern "C" void kernel_launch(void* const* d_in, const int* in_sizes, int n_in,
                              void* d_out, int out_size)
{
    const float* x  = (const float*)d_in[0];
    const float* Wk = (const float*)d_in[1];
    const float* Wq = (const float*)d_in[2];
    const float* Wv = (const float*)d_in[3];

    float* out  = (float*)d_out;
    float* kout = out + (size_t)BTH;
    float* vout = out + 2 * (size_t)BTH;

    cudaFuncSetAttribute(fused_head, cudaFuncAttributeMaxDynamicSharedMemorySize, FUSED_SMEM);
    fused_head<<<BB, 256, FUSED_SMEM>>>(x, Wk, Wq, Wv, out, kout, vout);
}

// round 10
// speedup vs baseline: 1.2022x; 1.0504x over previous
#include <cuda_runtime.h>
#include <cuda_fp16.h>
#include <cstdint>

#define BB 512
#define TT 256
#define CC 128
#define HH 128
#define BTH (BB * TT * HH)   // 16,777,216

// q fp16 scratch (cross-warp layout exchange; L2-hot)
__device__ __half g_qh[(size_t)BTH];  // q * QSCALE, [b][t][h]

__device__ __forceinline__ uint32_t h2bits(float a, float b) {
    __half2 h = __floats2half2_rn(a, b);
    return *(uint32_t*)&h;
}
__device__ __forceinline__ uint32_t smem_u32(const void* p) {
    uint32_t a;
    asm("{ .reg .u64 t; cvta.to.shared.u64 t, %1; cvt.u32.u64 %0, t; }" : "=r"(a) : "l"(p));
    return a;
}

// m16n8k16 fp16 MMA, fp32 accumulate in place
__device__ __forceinline__ void mma_f16(float acc[4], const uint32_t a[4],
                                        uint32_t b0, uint32_t b1) {
    asm volatile(
        "mma.sync.aligned.m16n8k16.row.col.f32.f16.f16.f32 "
        "{%0,%1,%2,%3}, {%4,%5,%6,%7}, {%8,%9}, {%0,%1,%2,%3};"
        : "+f"(acc[0]), "+f"(acc[1]), "+f"(acc[2]), "+f"(acc[3])
        : "r"(a[0]), "r"(a[1]), "r"(a[2]), "r"(a[3]), "r"(b0), "r"(b1));
}

// ldmatrix x4: four 8x8 b16 tiles, one shared-pipe op
__device__ __forceinline__ void ldsm_x4(uint32_t r[4], uint32_t addr) {
    asm volatile("ldmatrix.sync.aligned.m8n8.x4.shared.b16 {%0,%1,%2,%3}, [%4];"
                 : "=r"(r[0]), "=r"(r[1]), "=r"(r[2]), "=r"(r[3]) : "r"(addr));
}

// scale * log2(e): softmax computed base-2; folded into q at projection time
#define QSCALE (0.08838834764831845f * 1.4426950408889634f)

// ===========================================================================
// Fused kernel: one CTA per batch (512 CTAs, 256 threads), ldmatrix operands.
// smem halves: xbuf[128][136] + Wbuf[128][136] + ksm[256][136] + vtsm[128][264]
// ===========================================================================
#define LWB 136
#define LVT 264
#define XBUF_OFF 0
#define WBUF_OFF (128 * LWB)
#define KSM_OFF  (WBUF_OFF + 128 * LWB)
#define VT_OFF   (KSM_OFF + 256 * LWB)
#define FUSED_SMEM ((VT_OFF + 128 * LVT) * 2)
#define NEG_BIG (-1.0e30f)

__device__ __forceinline__ void load_w_t(const float* __restrict__ W,
                                         __half* __restrict__ ws, int tid) {
#pragma unroll
    for (int j = 0; j < 16; j++) {
        int i  = tid + j * 256;        // 0..4095
        int n  = i & 127;
        int kq = i >> 7;               // 0..31
        float w0 = W[(kq * 4 + 0) * HH + n];
        float w1 = W[(kq * 4 + 1) * HH + n];
        float w2 = W[(kq * 4 + 2) * HH + n];
        float w3 = W[(kq * 4 + 3) * HH + n];
        uint2 p = {h2bits(w0, w1), h2bits(w2, w3)};
        *(uint2*)&ws[n * LWB + kq * 4] = p;
    }
}

__global__ void __launch_bounds__(256, 1)
fused_head(const float* __restrict__ x,
           const float* __restrict__ Wk,
           const float* __restrict__ Wq,
           const float* __restrict__ Wv,
           float* __restrict__ outg,
           float* __restrict__ kout,
           float* __restrict__ vout)
{
    extern __shared__ __half smh[];
    __half* xbuf = smh + XBUF_OFF;    // [128][136]
    __half* Wbuf = smh + WBUF_OFF;    // [128][136]
    __half* ksm  = smh + KSM_OFF;     // [256][136]
    __half* vtsm = smh + VT_OFF;      // [128][264]

    const int tid  = threadIdx.x;
    const int b    = blockIdx.x;
    const int w    = tid >> 5;
    const int lane = tid & 31;
    const int g    = lane >> 2;
    const int c    = lane & 3;
    const int mbase = (w >> 1) * 32;
    const int nbase = (w & 1) * 64;
    const int rb   = w * 16;

    // ldmatrix per-lane address patterns (in halves)
    const int arow = (lane & 7) + ((lane >> 3) & 1) * 8;   // A tiles
    const int acol = (lane >> 4) * 8;
    const int brow = (lane & 7) + (lane >> 4) * 8;         // B tiles
    const int bcol = ((lane >> 3) & 1) * 8;

    const uint32_t xs_a = smem_u32(xbuf);
    const uint32_t wb_a = smem_u32(Wbuf);
    const uint32_t ks_a = smem_u32(ksm);
    const uint32_t vt_a = smem_u32(vtsm);

    // =======================================================================
    // Phase P: projection
    // =======================================================================
    const uint32_t xa_base = xs_a + (uint32_t)((mbase + arow) * LWB + acol) * 2u;
    const uint32_t wbB_base = wb_a + (uint32_t)((nbase + brow) * LWB + bcol) * 2u;

#pragma unroll 1
    for (int half = 0; half < 2; half++) {
        __syncthreads();

        // x half-tile -> xbuf (fp16)
        {
            const float4* xg = (const float4*)(x + ((size_t)b * TT + half * 128) * CC);
#pragma unroll
            for (int j = 0; j < 16; j++) {
                int i4 = tid + j * 256;
                float4 v = xg[i4];
                int row = i4 >> 5;
                int c4  = (i4 & 31) * 4;
                uint2 p = {h2bits(v.x, v.y), h2bits(v.z, v.w)};
                *(uint2*)&xbuf[row * LWB + c4] = p;
            }
        }

#pragma unroll 1
        for (int ph = 0; ph < 3; ph++) {
            __syncthreads();
            load_w_t(ph == 0 ? Wk : (ph == 1 ? Wq : Wv), Wbuf, tid);
            __syncthreads();

            float acc[2][8][4];
#pragma unroll
            for (int mt = 0; mt < 2; mt++)
#pragma unroll
                for (int nt = 0; nt < 8; nt++)
#pragma unroll
                    for (int e = 0; e < 4; e++) acc[mt][nt][e] = 0.0f;

#pragma unroll
            for (int kk = 0; kk < 8; kk++) {
                uint32_t a0[4], a1[4];
                ldsm_x4(a0, xa_base + (uint32_t)kk * 32u);
                ldsm_x4(a1, xa_base + 16u * LWB * 2u + (uint32_t)kk * 32u);
#pragma unroll
                for (int ntp = 0; ntp < 4; ntp++) {
                    uint32_t b4[4];
                    ldsm_x4(b4, wbB_base + (uint32_t)(ntp * 16 * LWB) * 2u + (uint32_t)kk * 32u);
                    mma_f16(acc[0][2 * ntp],     a0, b4[0], b4[1]);
                    mma_f16(acc[1][2 * ntp],     a1, b4[0], b4[1]);
                    mma_f16(acc[0][2 * ntp + 1], a0, b4[2], b4[3]);
                    mma_f16(acc[1][2 * ntp + 1], a1, b4[2], b4[3]);
                }
            }

            // epilogue
#pragma unroll
            for (int mt = 0; mt < 2; mt++) {
#pragma unroll
                for (int nt = 0; nt < 8; nt++) {
                    int rloc = mbase + mt * 16 + g;
                    int t    = half * 128 + rloc;
                    int grow = b * TT + t;
                    int col  = nbase + nt * 8 + 2 * c;
                    const float* v4 = acc[mt][nt];
                    if (ph == 0) {          // k
                        *(float2*)(kout + (size_t)grow * HH + col)       = make_float2(v4[0], v4[1]);
                        *(float2*)(kout + (size_t)(grow + 8) * HH + col) = make_float2(v4[2], v4[3]);
                        *(uint32_t*)&ksm[t * LWB + col]       = h2bits(v4[0], v4[1]);
                        *(uint32_t*)&ksm[(t + 8) * LWB + col] = h2bits(v4[2], v4[3]);
                    } else if (ph == 1) {   // q (pre-scaled)
                        *(uint32_t*)&g_qh[(size_t)grow * HH + col]       = h2bits(v4[0] * QSCALE, v4[1] * QSCALE);
                        *(uint32_t*)&g_qh[(size_t)(grow + 8) * HH + col] = h2bits(v4[2] * QSCALE, v4[3] * QSCALE);
                    } else {                // v
                        *(float2*)(vout + (size_t)grow * HH + col)       = make_float2(v4[0], v4[1]);
                        *(float2*)(vout + (size_t)(grow + 8) * HH + col) = make_float2(v4[2], v4[3]);
                        vtsm[(col    ) * LVT + t]     = __float2half_rn(v4[0]);
                        vtsm[(col + 1) * LVT + t]     = __float2half_rn(v4[1]);
                        vtsm[(col    ) * LVT + t + 8] = __float2half_rn(v4[2]);
                        vtsm[(col + 1) * LVT + t + 8] = __float2half_rn(v4[3]);
                    }
                }
            }
        }
    }
    __syncthreads();   // ksm/vtsm complete; g_qh visible within CTA

    // =======================================================================
    // Phase A: causal flash attention (K/V resident in smem, P in registers)
    // =======================================================================
    const uint32_t ksB_base = ks_a + (uint32_t)(brow * LWB + bcol) * 2u;
    const uint32_t vtB_base = vt_a + (uint32_t)(brow * LVT + bcol) * 2u;

#pragma unroll 1
    for (int qt = 0; qt < 2; qt++) {
        // Q fragments -> registers
        uint32_t aq[8][4];
        {
            const __half* q0 = g_qh + ((size_t)b * TT + qt * 128 + rb + g) * HH + 2 * c;
            const __half* q1 = q0 + 8 * HH;
#pragma unroll
            for (int kk = 0; kk < 8; kk++) {
                aq[kk][0] = *(const uint32_t*)(q0 + kk * 16);
                aq[kk][1] = *(const uint32_t*)(q1 + kk * 16);
                aq[kk][2] = *(const uint32_t*)(q0 + kk * 16 + 8);
                aq[kk][3] = *(const uint32_t*)(q1 + kk * 16 + 8);
            }
        }

        float m0 = NEG_BIG, m1 = NEG_BIG, l0 = 0.0f, l1 = 0.0f;
        float o[16][4];
#pragma unroll
        for (int nt = 0; nt < 16; nt++)
#pragma unroll
            for (int e = 0; e < 4; e++) o[nt][e] = 0.0f;

        const int row0 = qt * 128 + rb + g;
        const int row1 = row0 + 8;
        const int nkt  = 2 * (qt + 1);

#pragma unroll 1
        for (int kt = 0; kt < nkt; kt++) {
            // ---- S = Q K^T (B via ldmatrix from resident ksm) ----
            float s[8][4];
#pragma unroll
            for (int nt = 0; nt < 8; nt++)
#pragma unroll
                for (int e = 0; e < 4; e++) s[nt][e] = 0.0f;

            const uint32_t kbase = ksB_base + (uint32_t)(kt * 64 * LWB) * 2u;
#pragma unroll
            for (int kk = 0; kk < 8; kk++) {
#pragma unroll
                for (int ntp = 0; ntp < 4; ntp++) {
                    uint32_t b4[4];
                    ldsm_x4(b4, kbase + (uint32_t)(ntp * 16 * LWB) * 2u + (uint32_t)kk * 32u);
                    mma_f16(s[2 * ntp],     aq[kk], b4[0], b4[1]);
                    mma_f16(s[2 * ntp + 1], aq[kk], b4[2], b4[3]);
                }
            }

            // ---- causal mask + online softmax (base 2, Q pre-scaled) ----
            float mx0 = NEG_BIG, mx1 = NEG_BIG;
#pragma unroll
            for (int nt = 0; nt < 8; nt++) {
                int k0 = kt * 64 + nt * 8 + 2 * c;
                s[nt][0] = (k0     <= row0) ? s[nt][0] : NEG_BIG;
                s[nt][1] = (k0 + 1 <= row0) ? s[nt][1] : NEG_BIG;
                s[nt][2] = (k0     <= row1) ? s[nt][2] : NEG_BIG;
                s[nt][3] = (k0 + 1 <= row1) ? s[nt][3] : NEG_BIG;
                mx0 = fmaxf(mx0, fmaxf(s[nt][0], s[nt][1]));
                mx1 = fmaxf(mx1, fmaxf(s[nt][2], s[nt][3]));
            }
#pragma unroll
            for (int off = 1; off < 4; off <<= 1) {
                mx0 = fmaxf(mx0, __shfl_xor_sync(0xffffffffu, mx0, off));
                mx1 = fmaxf(mx1, __shfl_xor_sync(0xffffffffu, mx1, off));
            }
            float mn0 = fmaxf(m0, mx0);
            float mn1 = fmaxf(m1, mx1);
            float al0 = exp2f(m0 - mn0);
            float al1 = exp2f(m1 - mn1);
            float ps0 = 0.0f, ps1 = 0.0f;
#pragma unroll
            for (int nt = 0; nt < 8; nt++) {
                s[nt][0] = exp2f(s[nt][0] - mn0);
                s[nt][1] = exp2f(s[nt][1] - mn0);
                s[nt][2] = exp2f(s[nt][2] - mn1);
                s[nt][3] = exp2f(s[nt][3] - mn1);
                ps0 += s[nt][0] + s[nt][1];
                ps1 += s[nt][2] + s[nt][3];
            }
#pragma unroll
            for (int off = 1; off < 4; off <<= 1) {
                ps0 += __shfl_xor_sync(0xffffffffu, ps0, off);
                ps1 += __shfl_xor_sync(0xffffffffu, ps1, off);
            }
            l0 = l0 * al0 + ps0;
            l1 = l1 * al1 + ps1;
            m0 = mn0;
            m1 = mn1;
#pragma unroll
            for (int nt = 0; nt < 16; nt++) {
                o[nt][0] *= al0;
                o[nt][1] *= al0;
                o[nt][2] *= al1;
                o[nt][3] *= al1;
            }

            // ---- O += P @ V : P packed straight from s (no smem) ----
            const uint32_t vbase = vtB_base + (uint32_t)(kt * 64) * 2u;
#pragma unroll
            for (int kk = 0; kk < 4; kk++) {
                uint32_t pa[4];
                pa[0] = h2bits(s[2 * kk][0],     s[2 * kk][1]);
                pa[1] = h2bits(s[2 * kk][2],     s[2 * kk][3]);
                pa[2] = h2bits(s[2 * kk + 1][0], s[2 * kk + 1][1]);
                pa[3] = h2bits(s[2 * kk + 1][2], s[2 * kk + 1][3]);
#pragma unroll
                for (int ntp = 0; ntp < 8; ntp++) {
                    uint32_t b4[4];
                    ldsm_x4(b4, vbase + (uint32_t)(ntp * 16 * LVT) * 2u + (uint32_t)kk * 32u);
                    mma_f16(o[2 * ntp],     pa, b4[0], b4[1]);
                    mma_f16(o[2 * ntp + 1], pa, b4[2], b4[3]);
                }
            }
        }

        // ---- normalize + write ----
        float inv0 = 1.0f / l0;
        float inv1 = 1.0f / l1;
        float* orow0 = outg + ((size_t)b * TT + qt * 128 + rb + g) * HH;
        float* orow1 = orow0 + 8 * HH;
#pragma unroll
        for (int nt = 0; nt < 16; nt++) {
            int col = nt * 8 + 2 * c;
            *(float2*)(orow0 + col) = make_float2(o[nt][0] * inv0, o[nt][1] * inv0);
            *(float2*)(orow1 + col) = make_float2(o[nt][2] * inv1, o[nt][3] * inv1);
        }
    }
}

// ===========================================================================
extern "C" void kernel_launch(void* const* d_in, const int* in_sizes, int n_in,
                              void* d_out, int out_size)
{
    const float* x  = (const float*)d_in[0];
    const float* Wk = (const float*)d_in[1];
    const float* Wq = (const float*)d_in[2];
    const float* Wv = (const float*)d_in[3];

    float* out  = (float*)d_out;
    float* kout = out + (size_t)BTH;
    float* vout = out + 2 * (size_t)BTH;

    cudaFuncSetAttribute(fused_head, cudaFuncAttributeMaxDynamicSharedMemorySize, FUSED_SMEM);
    fused_head<<<BB, 256, FUSED_SMEM>>>(x, Wk, Wq, Wv, out, kout, vout);
}

// round 11
// speedup vs baseline: 1.2282x; 1.0216x over previous
#include <cuda_runtime.h>
#include <cuda_fp16.h>
#include <cstdint>

#define BB 512
#define TT 256
#define CC 128
#define HH 128
#define BTH (BB * TT * HH)   // 16,777,216

// q fp16 scratch (cross-warp layout exchange; L2-hot)
__device__ __half g_qh[(size_t)BTH];  // q * QSCALE, [b][t][h]

__device__ __forceinline__ uint32_t h2bits(float a, float b) {
    __half2 h = __floats2half2_rn(a, b);
    return *(uint32_t*)&h;
}
__device__ __forceinline__ uint32_t smem_u32(const void* p) {
    uint32_t a;
    asm("{ .reg .u64 t; cvta.to.shared.u64 t, %1; cvt.u32.u64 %0, t; }" : "=r"(a) : "l"(p));
    return a;
}

// m16n8k16 fp16 MMA, fp32 accumulate in place
__device__ __forceinline__ void mma_f16(float acc[4], const uint32_t a[4],
                                        uint32_t b0, uint32_t b1) {
    asm volatile(
        "mma.sync.aligned.m16n8k16.row.col.f32.f16.f16.f32 "
        "{%0,%1,%2,%3}, {%4,%5,%6,%7}, {%8,%9}, {%0,%1,%2,%3};"
        : "+f"(acc[0]), "+f"(acc[1]), "+f"(acc[2]), "+f"(acc[3])
        : "r"(a[0]), "r"(a[1]), "r"(a[2]), "r"(a[3]), "r"(b0), "r"(b1));
}

// ldmatrix x4: four 8x8 b16 tiles, one shared-pipe op
__device__ __forceinline__ void ldsm_x4(uint32_t r[4], uint32_t addr) {
    asm volatile("ldmatrix.sync.aligned.m8n8.x4.shared.b16 {%0,%1,%2,%3}, [%4];"
                 : "=r"(r[0]), "=r"(r[1]), "=r"(r[2]), "=r"(r[3]) : "r"(addr));
}

// scale * log2(e): softmax computed base-2; folded into q at projection time
#define QSCALE (0.08838834764831845f * 1.4426950408889634f)

// ===========================================================================
// Fused kernel: one CTA per batch, 512 threads (16 warps, 4/SMSP).
//   Phase P: projection, warp w = m-group (w>>1), n-group (w&1).
//   Phase A: warp w owns q-rows w*16..+15, nkt = w/4+1 key tiles (causal,
//            per-SMSP balanced). Q via qsm overlay (on xbuf+Wbuf).
// smem halves: xbuf[128][136] + Wbuf[128][136] + ksm[256][136] + vtsm[128][264]
// ===========================================================================
#define THREADS 512
#define LWB 136
#define LVT 264
#define XBUF_OFF 0
#define WBUF_OFF (128 * LWB)
#define KSM_OFF  (WBUF_OFF + 128 * LWB)
#define VT_OFF   (KSM_OFF + 256 * LWB)
#define FUSED_SMEM ((VT_OFF + 128 * LVT) * 2)
#define NEG_BIG (-1.0e30f)

__device__ __forceinline__ void load_w_t(const float* __restrict__ W,
                                         __half* __restrict__ ws, int tid) {
#pragma unroll
    for (int j = 0; j < 8; j++) {
        int i  = tid + j * THREADS;    // 0..4095
        int n  = i & 127;
        int kq = i >> 7;               // 0..31
        float w0 = W[(kq * 4 + 0) * HH + n];
        float w1 = W[(kq * 4 + 1) * HH + n];
        float w2 = W[(kq * 4 + 2) * HH + n];
        float w3 = W[(kq * 4 + 3) * HH + n];
        uint2 p = {h2bits(w0, w1), h2bits(w2, w3)};
        *(uint2*)&ws[n * LWB + kq * 4] = p;
    }
}

__global__ void __launch_bounds__(THREADS, 1)
fused_head(const float* __restrict__ x,
           const float* __restrict__ Wk,
           const float* __restrict__ Wq,
           const float* __restrict__ Wv,
           float* __restrict__ outg,
           float* __restrict__ kout,
           float* __restrict__ vout)
{
    extern __shared__ __half smh[];
    __half* xbuf = smh + XBUF_OFF;    // [128][136]
    __half* Wbuf = smh + WBUF_OFF;    // [128][136]
    __half* ksm  = smh + KSM_OFF;     // [256][136]
    __half* vtsm = smh + VT_OFF;      // [128][264]
    __half* qsm  = smh + XBUF_OFF;    // overlay after proj: [256][136]

    const int tid  = threadIdx.x;
    const int b    = blockIdx.x;
    const int w    = tid >> 5;        // 0..15
    const int lane = tid & 31;
    const int g    = lane >> 2;
    const int c    = lane & 3;
    const int mbase = (w >> 1) * 16;  // proj m-group (8 groups of 16 rows)
    const int nbase = (w & 1) * 64;   // proj n-group
    const int rb   = w * 16;          // attn q-row base (0..240)

    // ldmatrix per-lane address patterns (in halves)
    const int arow = (lane & 7) + ((lane >> 3) & 1) * 8;   // A tiles (m16k16)
    const int acol = (lane >> 4) * 8;
    const int brow = (lane & 7) + (lane >> 4) * 8;         // B tiles (k16n8x2)
    const int bcol = ((lane >> 3) & 1) * 8;

    const uint32_t xs_a = smem_u32(xbuf);
    const uint32_t wb_a = smem_u32(Wbuf);
    const uint32_t ks_a = smem_u32(ksm);
    const uint32_t vt_a = smem_u32(vtsm);

    // =======================================================================
    // Phase P: projection
    // =======================================================================
    const uint32_t xa_base  = xs_a + (uint32_t)((mbase + arow) * LWB + acol) * 2u;
    const uint32_t wbB_base = wb_a + (uint32_t)((nbase + brow) * LWB + bcol) * 2u;

#pragma unroll 1
    for (int half = 0; half < 2; half++) {
        __syncthreads();

        // x half-tile -> xbuf (fp16)
        {
            const float4* xg = (const float4*)(x + ((size_t)b * TT + half * 128) * CC);
#pragma unroll
            for (int j = 0; j < 8; j++) {
                int i4 = tid + j * THREADS;
                float4 v = xg[i4];
                int row = i4 >> 5;
                int c4  = (i4 & 31) * 4;
                uint2 p = {h2bits(v.x, v.y), h2bits(v.z, v.w)};
                *(uint2*)&xbuf[row * LWB + c4] = p;
            }
        }

#pragma unroll 1
        for (int ph = 0; ph < 3; ph++) {
            __syncthreads();
            load_w_t(ph == 0 ? Wk : (ph == 1 ? Wq : Wv), Wbuf, tid);
            __syncthreads();

            float acc[8][4];
#pragma unroll
            for (int nt = 0; nt < 8; nt++)
#pragma unroll
                for (int e = 0; e < 4; e++) acc[nt][e] = 0.0f;

#pragma unroll
            for (int kk = 0; kk < 8; kk++) {
                uint32_t a0[4];
                ldsm_x4(a0, xa_base + (uint32_t)kk * 32u);
#pragma unroll
                for (int ntp = 0; ntp < 4; ntp++) {
                    uint32_t b4[4];
                    ldsm_x4(b4, wbB_base + (uint32_t)(ntp * 16 * LWB) * 2u + (uint32_t)kk * 32u);
                    mma_f16(acc[2 * ntp],     a0, b4[0], b4[1]);
                    mma_f16(acc[2 * ntp + 1], a0, b4[2], b4[3]);
                }
            }

            // epilogue (warp rows: mbase+g, mbase+g+8)
#pragma unroll
            for (int nt = 0; nt < 8; nt++) {
                int rloc = mbase + g;
                int t    = half * 128 + rloc;
                int grow = b * TT + t;
                int col  = nbase + nt * 8 + 2 * c;
                const float* v4 = acc[nt];
                if (ph == 0) {          // k
                    *(float2*)(kout + (size_t)grow * HH + col)       = make_float2(v4[0], v4[1]);
                    *(float2*)(kout + (size_t)(grow + 8) * HH + col) = make_float2(v4[2], v4[3]);
                    *(uint32_t*)&ksm[t * LWB + col]       = h2bits(v4[0], v4[1]);
                    *(uint32_t*)&ksm[(t + 8) * LWB + col] = h2bits(v4[2], v4[3]);
                } else if (ph == 1) {   // q (pre-scaled)
                    *(uint32_t*)&g_qh[(size_t)grow * HH + col]       = h2bits(v4[0] * QSCALE, v4[1] * QSCALE);
                    *(uint32_t*)&g_qh[(size_t)(grow + 8) * HH + col] = h2bits(v4[2] * QSCALE, v4[3] * QSCALE);
                } else {                // v
                    *(float2*)(vout + (size_t)grow * HH + col)       = make_float2(v4[0], v4[1]);
                    *(float2*)(vout + (size_t)(grow + 8) * HH + col) = make_float2(v4[2], v4[3]);
                    vtsm[(col    ) * LVT + t]     = __float2half_rn(v4[0]);
                    vtsm[(col + 1) * LVT + t]     = __float2half_rn(v4[1]);
                    vtsm[(col    ) * LVT + t + 8] = __float2half_rn(v4[2]);
                    vtsm[(col + 1) * LVT + t + 8] = __float2half_rn(v4[3]);
                }
            }
        }
    }
    __syncthreads();   // proj done; xbuf/Wbuf free; g_qh visible within CTA

    // ---- copy this batch's q into qsm overlay ([256][136]) ----
    {
        const __half* qg = g_qh + (size_t)b * TT * HH;
#pragma unroll
        for (int j = 0; j < 8; j++) {
            int i4  = tid + j * THREADS;      // 0..4095 chunks of 8 halves
            int row = i4 >> 4;
            int c8  = (i4 & 15) * 8;
            *(uint4*)&qsm[row * LWB + c8] = *(const uint4*)&qg[(size_t)row * HH + c8];
        }
    }
    __syncthreads();

    // =======================================================================
    // Phase A: causal flash attention; warp w: rows rb..rb+15, nkt = w/4+1
    // =======================================================================
    const uint32_t qa_base  = smem_u32(qsm) + (uint32_t)((rb + arow) * LWB + acol) * 2u;
    const uint32_t ksB_base = ks_a + (uint32_t)(brow * LWB + bcol) * 2u;
    const uint32_t vtB_base = vt_a + (uint32_t)(brow * LVT + bcol) * 2u;

    float m0 = NEG_BIG, m1 = NEG_BIG, l0 = 0.0f, l1 = 0.0f;
    float o[16][4];
#pragma unroll
    for (int nt = 0; nt < 16; nt++)
#pragma unroll
        for (int e = 0; e < 4; e++) o[nt][e] = 0.0f;

    const int row0 = rb + g;
    const int row1 = row0 + 8;
    const int nkt  = (w >> 2) + 1;

#pragma unroll 1
    for (int kt = 0; kt < nkt; kt++) {
        // ---- S = Q K^T ----
        float s[8][4];
#pragma unroll
        for (int nt = 0; nt < 8; nt++)
#pragma unroll
            for (int e = 0; e < 4; e++) s[nt][e] = 0.0f;

        const uint32_t kbase = ksB_base + (uint32_t)(kt * 64 * LWB) * 2u;
#pragma unroll
        for (int kk = 0; kk < 8; kk++) {
            uint32_t aq[4];
            ldsm_x4(aq, qa_base + (uint32_t)kk * 32u);
#pragma unroll
            for (int ntp = 0; ntp < 4; ntp++) {
                uint32_t b4[4];
                ldsm_x4(b4, kbase + (uint32_t)(ntp * 16 * LWB) * 2u + (uint32_t)kk * 32u);
                mma_f16(s[2 * ntp],     aq, b4[0], b4[1]);
                mma_f16(s[2 * ntp + 1], aq, b4[2], b4[3]);
            }
        }

        // ---- causal mask + online softmax (base 2, Q pre-scaled) ----
        float mx0 = NEG_BIG, mx1 = NEG_BIG;
#pragma unroll
        for (int nt = 0; nt < 8; nt++) {
            int k0 = kt * 64 + nt * 8 + 2 * c;
            s[nt][0] = (k0     <= row0) ? s[nt][0] : NEG_BIG;
            s[nt][1] = (k0 + 1 <= row0) ? s[nt][1] : NEG_BIG;
            s[nt][2] = (k0     <= row1) ? s[nt][2] : NEG_BIG;
            s[nt][3] = (k0 + 1 <= row1) ? s[nt][3] : NEG_BIG;
            mx0 = fmaxf(mx0, fmaxf(s[nt][0], s[nt][1]));
            mx1 = fmaxf(mx1, fmaxf(s[nt][2], s[nt][3]));
        }
#pragma unroll
        for (int off = 1; off < 4; off <<= 1) {
            mx0 = fmaxf(mx0, __shfl_xor_sync(0xffffffffu, mx0, off));
            mx1 = fmaxf(mx1, __shfl_xor_sync(0xffffffffu, mx1, off));
        }
        float mn0 = fmaxf(m0, mx0);
        float mn1 = fmaxf(m1, mx1);
        float al0 = exp2f(m0 - mn0);
        float al1 = exp2f(m1 - mn1);
        float ps0 = 0.0f, ps1 = 0.0f;
#pragma unroll
        for (int nt = 0; nt < 8; nt++) {
            s[nt][0] = exp2f(s[nt][0] - mn0);
            s[nt][1] = exp2f(s[nt][1] - mn0);
            s[nt][2] = exp2f(s[nt][2] - mn1);
            s[nt][3] = exp2f(s[nt][3] - mn1);
            ps0 += s[nt][0] + s[nt][1];
            ps1 += s[nt][2] + s[nt][3];
        }
#pragma unroll
        for (int off = 1; off < 4; off <<= 1) {
            ps0 += __shfl_xor_sync(0xffffffffu, ps0, off);
            ps1 += __shfl_xor_sync(0xffffffffu, ps1, off);
        }
        l0 = l0 * al0 + ps0;
        l1 = l1 * al1 + ps1;
        m0 = mn0;
        m1 = mn1;
#pragma unroll
        for (int nt = 0; nt < 16; nt++) {
            o[nt][0] *= al0;
            o[nt][1] *= al0;
            o[nt][2] *= al1;
            o[nt][3] *= al1;
        }

        // ---- O += P @ V : P packed straight from s ----
        const uint32_t vbase = vtB_base + (uint32_t)(kt * 64) * 2u;
#pragma unroll
        for (int kk = 0; kk < 4; kk++) {
            uint32_t pa[4];
            pa[0] = h2bits(s[2 * kk][0],     s[2 * kk][1]);
            pa[1] = h2bits(s[2 * kk][2],     s[2 * kk][3]);
            pa[2] = h2bits(s[2 * kk + 1][0], s[2 * kk + 1][1]);
            pa[3] = h2bits(s[2 * kk + 1][2], s[2 * kk + 1][3]);
#pragma unroll
            for (int ntp = 0; ntp < 8; ntp++) {
                uint32_t b4[4];
                ldsm_x4(b4, vbase + (uint32_t)(ntp * 16 * LVT) * 2u + (uint32_t)kk * 32u);
                mma_f16(o[2 * ntp],     pa, b4[0], b4[1]);
                mma_f16(o[2 * ntp + 1], pa, b4[2], b4[3]);
            }
        }
    }

    // ---- normalize + write ----
    float inv0 = 1.0f / l0;
    float inv1 = 1.0f / l1;
    float* orow0 = outg + ((size_t)b * TT + rb + g) * HH;
    float* orow1 = orow0 + 8 * HH;
#pragma unroll
    for (int nt = 0; nt < 16; nt++) {
        int col = nt * 8 + 2 * c;
        *(float2*)(orow0 + col) = make_float2(o[nt][0] * inv0, o[nt][1] * inv0);
        *(float2*)(orow1 + col) = make_float2(o[nt][2] * inv1, o[nt][3] * inv1);
    }
}

// ===========================================================================
extern "C" void kernel_launch(void* const* d_in, const int* in_sizes, int n_in,
                              void* d_out, int out_size)
{
    const float* x  = (const float*)d_in[0];
    const float* Wk = (const float*)d_in[1];
    const float* Wq = (const float*)d_in[2];
    const float* Wv = (const float*)d_in[3];

    float* out  = (float*)d_out;
    float* kout = out + (size_t)BTH;
    float* vout = out + 2 * (size_t)BTH;

    cudaFuncSetAttribute(fused_head, cudaFuncAttributeMaxDynamicSharedMemorySize, FUSED_SMEM);
    fused_head<<<BB, THREADS, FUSED_SMEM>>>(x, Wk, Wq, Wv, out, kout, vout);
}